// round 13
// baseline (speedup 1.0000x reference)
#include <cuda_runtime.h>
#include <cuda_fp16.h>
#include <cstdint>
#include <math.h>

#define ENC 2048
#define DEC 512
#define ATTD 512
#define BATCH 256
#define LSEQ 196
#define MROWS (BATCH * LSEQ)      // 50176
#define TILE_M 128
#define NTILES (MROWS / TILE_M)   // 392
#define MAIN_CTAS 296             // 2 perfect waves on 148 SMs
#define TAIL_ROW0 (MAIN_CTAS * TILE_M)   // 37888
#define QTILES ((MROWS - TAIL_ROW0) / 32)  // 384 quarter tiles (M32)
#define KBLK 64
#define NKB (ENC / KBLK)          // 32
#define NB_CHUNKS 2               // 512 / 256
#define NSTG 3
#define XSTG 16384                // x: 128 rows x 64k x 2B (quarter uses 32 rows)
#define WSTG 32768                // W: 256 rows x 64k x 2B
#define WBASE (NSTG * XSTG)       // 49152
#define DYN_BYTES (WBASE + NSTG * WSTG + 128)    // 147584
#define NTHREADS 512

// ---------------- scratch globals ----------------
__device__ float g_att2[BATCH * ATTD];
__device__ float g_gate[BATCH];
__device__ float g_att[MROWS];
// W transposed fp16: [n=512][k=2048]
__device__ __align__(16) unsigned char g_Wt[512u * 2048u * 2u];

// ---------------- helpers ----------------
__device__ __forceinline__ uint32_t smem_u32(const void* p) {
    uint32_t a;
    asm("{ .reg .u64 t; cvta.to.shared.u64 t, %1; cvt.u32.u64 %0, t; }" : "=r"(a) : "l"(p));
    return a;
}
__device__ __forceinline__ uint32_t packh2(__half a, __half b) {
    __half2 t = __halves2half2(a, b);
    return *reinterpret_cast<uint32_t*>(&t);
}
#define LDSM_X4(r, addr) \
    asm volatile("ldmatrix.sync.aligned.m8n8.x4.shared.b16 {%0,%1,%2,%3}, [%4];" \
        : "=r"((r)[0]), "=r"((r)[1]), "=r"((r)[2]), "=r"((r)[3]) : "r"(addr))
#define MMA_F16F32(c, a, b) \
    asm volatile("mma.sync.aligned.m16n8k16.row.col.f32.f16.f16.f32 " \
        "{%0,%1,%2,%3}, {%4,%5,%6,%7}, {%8,%9}, {%0,%1,%2,%3};" \
        : "+f"((c)[0]), "+f"((c)[1]), "+f"((c)[2]), "+f"((c)[3]) \
        : "r"((a)[0]), "r"((a)[1]), "r"((a)[2]), "r"((a)[3]), "r"((b)[0]), "r"((b)[1]))
#define CP_ASYNC16(dst, src) \
    asm volatile("cp.async.ca.shared.global [%0], [%1], 16;" :: "r"(dst), "l"(src) : "memory")
#define CP_COMMIT() asm volatile("cp.async.commit_group;" ::: "memory")
#define CP_WAIT1()  asm volatile("cp.async.wait_group 1;" ::: "memory")
#define CP_WAIT0()  asm volatile("cp.async.wait_group 0;" ::: "memory")

// ---------------------------------------------------------------------------
// prep_w: W_enc [2048 k][512 n] fp32 -> g_Wt fp16 [n][k]
// ---------------------------------------------------------------------------
__global__ __launch_bounds__(256) void prep_w(const float* __restrict__ W_enc) {
    __shared__ float tile[64][65];
    const int k0 = blockIdx.x * 64, n0 = blockIdx.y * 64;
    const int tid = threadIdx.x;
    for (int i = tid; i < 64 * 64; i += 256) {
        int kk = i >> 6, nn = i & 63;
        tile[kk][nn] = W_enc[(size_t)(k0 + kk) * ATTD + n0 + nn];
    }
    __syncthreads();
    for (int i = tid; i < 512; i += 256) {
        int nn = i >> 3, ch = i & 7;
        uint32_t w[4];
#pragma unroll
        for (int j = 0; j < 4; j++) {
            w[j] = packh2(__float2half_rn(tile[ch * 8 + 2 * j][nn]),
                          __float2half_rn(tile[ch * 8 + 2 * j + 1][nn]));
        }
        *reinterpret_cast<uint4*>(g_Wt + (size_t)(n0 + nn) * 4096 +
                                  (size_t)(k0 + ch * 8) * 2) =
            make_uint4(w[0], w[1], w[2], w[3]);
    }
}

// ---------------------------------------------------------------------------
// att2 + gate
// ---------------------------------------------------------------------------
__global__ __launch_bounds__(256) void att2_kernel(
    const float* __restrict__ h, const float* __restrict__ W_dec,
    const float* __restrict__ b_dec, const float* __restrict__ b_enc,
    const float* __restrict__ W_beta, const float* __restrict__ b_beta) {
    int b = blockIdx.x, t = threadIdx.x;
    __shared__ float hs[DEC];
    __shared__ float red[256];
    hs[t] = h[b * DEC + t];
    hs[t + 256] = h[b * DEC + t + 256];
    __syncthreads();
    float acc0 = 0.f, acc1 = 0.f;
#pragma unroll 8
    for (int k = 0; k < DEC; k++) {
        float hv = hs[k];
        acc0 += hv * W_dec[k * ATTD + t];
        acc1 += hv * W_dec[k * ATTD + t + 256];
    }
    g_att2[b * ATTD + t] = acc0 + b_dec[t] + b_enc[t];
    g_att2[b * ATTD + t + 256] = acc1 + b_dec[t + 256] + b_enc[t + 256];
    float p = hs[t] * W_beta[t] + hs[t + 256] * W_beta[t + 256];
    red[t] = p;
    __syncthreads();
    for (int s = 128; s > 0; s >>= 1) {
        if (t < s) red[t] += red[t + s];
        __syncthreads();
    }
    if (t == 0) g_gate[b] = 1.f / (1.f + expf(-(red[0] + b_beta[0])));
}

// ---------------------------------------------------------------------------
// Combined GEMM: blocks 0..295 = M128 tiles (2 perfect waves);
// blocks 296..679 = M32 quarter tiles (tail, no x duplication, no atomics).
// Both paths: single-pass fp16 mma.sync, KBLK=64, 3 stages, W N256 chunks.
// ---------------------------------------------------------------------------
__global__ __launch_bounds__(NTHREADS, 1) void att_gemm_mma(
    const float* __restrict__ x, const float* __restrict__ W_full) {
    extern __shared__ unsigned char dynraw[];
    __shared__ float wf_s[ATTD];
    __shared__ float att_acc[TILE_M];

    const int tid = threadIdx.x;
    const int lane = tid & 31;
    const int wid = tid >> 5;

    uint32_t rawb = smem_u32(dynraw);
    uint32_t dynb = (rawb + 127u) & ~127u;
    unsigned char* dyn = dynraw + (dynb - rawb);

    wf_s[tid] = W_full[tid];
    if (tid < TILE_M) att_acc[tid] = 0.f;
    __syncthreads();

    if (blockIdx.x < MAIN_CTAS) {
        // ================= MAIN PATH: M128 x N512 =================
        const int wm = wid >> 2;   // 0..3
        const int wn = wid & 3;    // 0..3
        const int row0 = blockIdx.x * TILE_M;

        const int xm = tid >> 2, xq = tid & 3;
        const int xs7 = xm & 7;
        const float4* xg = reinterpret_cast<const float4*>(x) +
                           ((size_t)(row0 + xm) * ENC) / 4 + xq * 4;

        const int a_r = wm * 32 + (lane & 15);
        const int a_hi = lane >> 4;
        const int b_r = wn * 64 + (lane & 7) + ((lane >> 1) & 8);
        const int b_hi = (lane >> 3) & 1;

        for (int nb = 0; nb < NB_CHUNKS; nb++) {
            float acc[2][8][4];
#pragma unroll
            for (int mt = 0; mt < 2; mt++)
#pragma unroll
                for (int nt = 0; nt < 8; nt++)
#pragma unroll
                    for (int q = 0; q < 4; q++) acc[mt][nt][q] = 0.f;

            {   // x stage 0
                float4 v0 = xg[0], v1 = xg[1], v2 = xg[2], v3 = xg[3];
                float e[16] = {v0.x, v0.y, v0.z, v0.w, v1.x, v1.y, v1.z, v1.w,
                               v2.x, v2.y, v2.z, v2.w, v3.x, v3.y, v3.z, v3.w};
                uint32_t hw[8];
#pragma unroll
                for (int q = 0; q < 8; q++)
                    hw[q] = packh2(__float2half_rn(e[2 * q]), __float2half_rn(e[2 * q + 1]));
                int c0 = 2 * xq;
                *reinterpret_cast<uint4*>(dyn + xm * 128 + ((c0 ^ xs7) << 4)) =
                    make_uint4(hw[0], hw[1], hw[2], hw[3]);
                *reinterpret_cast<uint4*>(dyn + xm * 128 + (((c0 + 1) ^ xs7) << 4)) =
                    make_uint4(hw[4], hw[5], hw[6], hw[7]);
            }
#pragma unroll
            for (int p = 0; p < 2; p++) {
#pragma unroll
                for (int j = 0; j < 4; j++) {
                    int i = tid + NTHREADS * j;
                    int row = i >> 3, c = i & 7;
                    uint32_t dst = dynb + WBASE + p * WSTG + row * 128 + ((c ^ (row & 7)) << 4);
                    const unsigned char* src = g_Wt +
                        (size_t)(nb * 256 + row) * 4096 + (size_t)(p * KBLK + c * 8) * 2;
                    CP_ASYNC16(dst, src);
                }
                CP_COMMIT();
            }

            for (int kblk = 0; kblk < NKB; kblk++) {
                const int st = kblk % NSTG;
                const bool more = (kblk + 1 < NKB);
                float4 xr0, xr1, xr2, xr3;
                if (more) {
                    const float4* p = xg + (kblk + 1) * (KBLK / 4);
                    xr0 = p[0]; xr1 = p[1]; xr2 = p[2]; xr3 = p[3];
                }
                CP_WAIT1();
                __syncthreads();

                if (kblk + 2 < NKB) {
                    const int ws = (kblk + 2) % NSTG;
#pragma unroll
                    for (int j = 0; j < 4; j++) {
                        int i = tid + NTHREADS * j;
                        int row = i >> 3, c = i & 7;
                        uint32_t dst = dynb + WBASE + ws * WSTG + row * 128 +
                                       ((c ^ (row & 7)) << 4);
                        const unsigned char* src = g_Wt +
                            (size_t)(nb * 256 + row) * 4096 +
                            (size_t)((kblk + 2) * KBLK + c * 8) * 2;
                        CP_ASYNC16(dst, src);
                    }
                }
                CP_COMMIT();

                {
                    const uint32_t xsb = dynb + st * XSTG;
                    const uint32_t wsb = dynb + WBASE + st * WSTG;
#pragma unroll
                    for (int ks = 0; ks < 4; ks++) {
                        uint32_t ah[2][4];
#pragma unroll
                        for (int mt = 0; mt < 2; mt++) {
                            int row = a_r + mt * 16;
                            uint32_t ad = xsb + row * 128 +
                                          (((ks * 2 + a_hi) ^ (row & 7)) << 4);
                            LDSM_X4(ah[mt], ad);
                        }
#pragma unroll
                        for (int ntp = 0; ntp < 4; ntp++) {
                            int row = b_r + ntp * 16;
                            uint32_t bd = wsb + row * 128 +
                                          (((ks * 2 + b_hi) ^ (row & 7)) << 4);
                            uint32_t bh[4];
                            LDSM_X4(bh, bd);
#pragma unroll
                            for (int mt = 0; mt < 2; mt++) {
                                MMA_F16F32(acc[mt][2 * ntp],     ah[mt], bh + 0);
                                MMA_F16F32(acc[mt][2 * ntp + 1], ah[mt], bh + 2);
                            }
                        }
                    }
                }

                if (more) {
                    const int xs = (kblk + 1) % NSTG;
                    float e[16] = {xr0.x, xr0.y, xr0.z, xr0.w, xr1.x, xr1.y, xr1.z, xr1.w,
                                   xr2.x, xr2.y, xr2.z, xr2.w, xr3.x, xr3.y, xr3.z, xr3.w};
                    uint32_t hw[8];
#pragma unroll
                    for (int q = 0; q < 8; q++)
                        hw[q] = packh2(__float2half_rn(e[2 * q]), __float2half_rn(e[2 * q + 1]));
                    unsigned char* xb = dyn + xs * XSTG;
                    int c0 = 2 * xq;
                    *reinterpret_cast<uint4*>(xb + xm * 128 + ((c0 ^ xs7) << 4)) =
                        make_uint4(hw[0], hw[1], hw[2], hw[3]);
                    *reinterpret_cast<uint4*>(xb + xm * 128 + (((c0 + 1) ^ xs7) << 4)) =
                        make_uint4(hw[4], hw[5], hw[6], hw[7]);
                }
            }
            CP_WAIT0();
            __syncthreads();

#pragma unroll
            for (int mt = 0; mt < 2; mt++)
#pragma unroll
                for (int rh = 0; rh < 2; rh++) {
                    int ml = wm * 32 + mt * 16 + (lane >> 2) + rh * 8;
                    int gm = row0 + ml;
                    int b = gm / LSEQ;
                    const float* a2 = g_att2 + (size_t)b * ATTD + nb * 256 + wn * 64;
                    const float* wfp = wf_s + nb * 256 + wn * 64;
                    float s = 0.f;
#pragma unroll
                    for (int nt = 0; nt < 8; nt++) {
#pragma unroll
                        for (int e2 = 0; e2 < 2; e2++) {
                            int nn = nt * 8 + (lane & 3) * 2 + e2;
                            float v = acc[mt][nt][rh * 2 + e2] + __ldg(a2 + nn);
                            s += fmaxf(v, 0.f) * wfp[nn];
                        }
                    }
                    s += __shfl_xor_sync(0xFFFFFFFF, s, 1);
                    s += __shfl_xor_sync(0xFFFFFFFF, s, 2);
                    if ((lane & 3) == 0) atomicAdd(&att_acc[ml], s);
                }
            __syncthreads();
        }
        if (tid < TILE_M) g_att[row0 + tid] = att_acc[tid];

    } else {
        // ================= QUARTER PATH: M32 x N512 =================
        const int q = blockIdx.x - MAIN_CTAS;           // 0..383
        const int row0 = TAIL_ROW0 + q * 32;
        const int wm = wid >> 3;   // 0..1 (m16 each)
        const int wn = wid & 7;    // 0..7 (n32 per chunk)

        // x loader: 16 threads/row, each 4 fp32 -> 8B halves
        const int xm = tid >> 4, xq = tid & 15;
        const int xs7 = xm & 7;
        const float4* xg = reinterpret_cast<const float4*>(x) +
                           ((size_t)(row0 + xm) * ENC) / 4 + xq;
        const int xc = xq >> 1;            // 16B chunk within row
        const int xo = (xq & 1) * 8;       // byte offset within chunk

        const int a_r = wm * 16 + (lane & 15);
        const int a_hi = lane >> 4;
        const int b_r = wn * 32 + (lane & 7) + ((lane >> 1) & 8);
        const int b_hi = (lane >> 3) & 1;

        for (int nb = 0; nb < NB_CHUNKS; nb++) {
            float acc[4][4];
#pragma unroll
            for (int nt = 0; nt < 4; nt++)
#pragma unroll
                for (int p = 0; p < 4; p++) acc[nt][p] = 0.f;

            {   // x stage 0
                float4 v = xg[0];
                uint32_t h0 = packh2(__float2half_rn(v.x), __float2half_rn(v.y));
                uint32_t h1 = packh2(__float2half_rn(v.z), __float2half_rn(v.w));
                *reinterpret_cast<uint2*>(dyn + xm * 128 + ((xc ^ xs7) << 4) + xo) =
                    make_uint2(h0, h1);
            }
#pragma unroll
            for (int p = 0; p < 2; p++) {
#pragma unroll
                for (int j = 0; j < 4; j++) {
                    int i = tid + NTHREADS * j;
                    int row = i >> 3, c = i & 7;
                    uint32_t dst = dynb + WBASE + p * WSTG + row * 128 + ((c ^ (row & 7)) << 4);
                    const unsigned char* src = g_Wt +
                        (size_t)(nb * 256 + row) * 4096 + (size_t)(p * KBLK + c * 8) * 2;
                    CP_ASYNC16(dst, src);
                }
                CP_COMMIT();
            }

            for (int kblk = 0; kblk < NKB; kblk++) {
                const int st = kblk % NSTG;
                const bool more = (kblk + 1 < NKB);
                float4 xr;
                if (more) xr = xg[(kblk + 1) * (KBLK / 4)];
                CP_WAIT1();
                __syncthreads();

                if (kblk + 2 < NKB) {
                    const int ws = (kblk + 2) % NSTG;
#pragma unroll
                    for (int j = 0; j < 4; j++) {
                        int i = tid + NTHREADS * j;
                        int row = i >> 3, c = i & 7;
                        uint32_t dst = dynb + WBASE + ws * WSTG + row * 128 +
                                       ((c ^ (row & 7)) << 4);
                        const unsigned char* src = g_Wt +
                            (size_t)(nb * 256 + row) * 4096 +
                            (size_t)((kblk + 2) * KBLK + c * 8) * 2;
                        CP_ASYNC16(dst, src);
                    }
                }
                CP_COMMIT();

                {
                    const uint32_t xsb = dynb + st * XSTG;
                    const uint32_t wsb = dynb + WBASE + st * WSTG;
#pragma unroll
                    for (int ks = 0; ks < 4; ks++) {
                        uint32_t ah[4];
                        {
                            int row = a_r;
                            uint32_t ad = xsb + row * 128 +
                                          (((ks * 2 + a_hi) ^ (row & 7)) << 4);
                            LDSM_X4(ah, ad);
                        }
#pragma unroll
                        for (int ntp = 0; ntp < 2; ntp++) {
                            int row = b_r + ntp * 16;
                            uint32_t bd = wsb + row * 128 +
                                          (((ks * 2 + b_hi) ^ (row & 7)) << 4);
                            uint32_t bh[4];
                            LDSM_X4(bh, bd);
                            MMA_F16F32(acc[2 * ntp],     ah, bh + 0);
                            MMA_F16F32(acc[2 * ntp + 1], ah, bh + 2);
                        }
                    }
                }

                if (more) {
                    const int xs = (kblk + 1) % NSTG;
                    uint32_t h0 = packh2(__float2half_rn(xr.x), __float2half_rn(xr.y));
                    uint32_t h1 = packh2(__float2half_rn(xr.z), __float2half_rn(xr.w));
                    *reinterpret_cast<uint2*>(dyn + xs * XSTG + xm * 128 +
                                              ((xc ^ xs7) << 4) + xo) = make_uint2(h0, h1);
                }
            }
            CP_WAIT0();
            __syncthreads();

            // epilogue (rows 0..31)
#pragma unroll
            for (int rh = 0; rh < 2; rh++) {
                int ml = wm * 16 + (lane >> 2) + rh * 8;
                int gm = row0 + ml;
                int b = gm / LSEQ;
                const float* a2 = g_att2 + (size_t)b * ATTD + nb * 256 + wn * 32;
                const float* wfp = wf_s + nb * 256 + wn * 32;
                float s = 0.f;
#pragma unroll
                for (int nt = 0; nt < 4; nt++) {
#pragma unroll
                    for (int e2 = 0; e2 < 2; e2++) {
                        int nn = nt * 8 + (lane & 3) * 2 + e2;
                        float v = acc[nt][rh * 2 + e2] + __ldg(a2 + nn);
                        s += fmaxf(v, 0.f) * wfp[nn];
                    }
                }
                s += __shfl_xor_sync(0xFFFFFFFF, s, 1);
                s += __shfl_xor_sync(0xFFFFFFFF, s, 2);
                if ((lane & 3) == 0) atomicAdd(&att_acc[ml], s);
            }
            __syncthreads();
        }
        if (tid < 32) g_att[row0 + tid] = att_acc[tid];
    }
}

// ---------------------------------------------------------------------------
// fused softmax + z: one block per batch
// ---------------------------------------------------------------------------
__global__ __launch_bounds__(256) void softmax_z_kernel(
    const float* __restrict__ x, float* __restrict__ out_alpha,
    float* __restrict__ out_z) {
    int b = blockIdx.x, t = threadIdx.x;
    __shared__ float sred[256];
    __shared__ float sal[LSEQ];

    float v = (t < LSEQ) ? g_att[b * LSEQ + t] : -1e30f;
    sred[t] = v;
    __syncthreads();
    for (int s = 128; s > 0; s >>= 1) {
        if (t < s) sred[t] = fmaxf(sred[t], sred[t + s]);
        __syncthreads();
    }
    float m = sred[0];
    __syncthreads();
    float e = (t < LSEQ) ? expf(v - m) : 0.f;
    sred[t] = e;
    __syncthreads();
    for (int s = 128; s > 0; s >>= 1) {
        if (t < s) sred[t] += sred[t + s];
        __syncthreads();
    }
    float inv = 1.f / sred[0];
    if (t < LSEQ) {
        float a = e * inv;
        out_alpha[b * LSEQ + t] = a;
        sal[t] = a;
    }
    __syncthreads();

    const float4* xp = reinterpret_cast<const float4*>(x + (size_t)b * LSEQ * ENC);
    float4 a0 = {0.f, 0.f, 0.f, 0.f}, a1 = {0.f, 0.f, 0.f, 0.f};
#pragma unroll 2
    for (int l = 0; l < LSEQ; l++) {
        float a = sal[l];
        float4 v0 = __ldg(xp + (size_t)l * (ENC / 4) + t);
        float4 v1 = __ldg(xp + (size_t)l * (ENC / 4) + t + 256);
        a0.x += a * v0.x; a0.y += a * v0.y; a0.z += a * v0.z; a0.w += a * v0.w;
        a1.x += a * v1.x; a1.y += a * v1.y; a1.z += a * v1.z; a1.w += a * v1.w;
    }
    float g = g_gate[b];
    float4 o0 = {g * a0.x, g * a0.y, g * a0.z, g * a0.w};
    float4 o1 = {g * a1.x, g * a1.y, g * a1.z, g * a1.w};
    reinterpret_cast<float4*>(out_z)[(size_t)b * (ENC / 4) + t] = o0;
    reinterpret_cast<float4*>(out_z)[(size_t)b * (ENC / 4) + t + 256] = o1;
}

// ---------------------------------------------------------------------------
extern "C" void kernel_launch(void* const* d_in, const int* in_sizes, int n_in,
                              void* d_out, int out_size) {
    const float* x      = (const float*)d_in[0];
    const float* h      = (const float*)d_in[1];
    const float* W_enc  = (const float*)d_in[2];
    const float* b_enc  = (const float*)d_in[3];
    const float* W_dec  = (const float*)d_in[4];
    const float* b_dec  = (const float*)d_in[5];
    const float* W_full = (const float*)d_in[6];
    // d_in[7] = b_full: softmax-invariant, unused.
    const float* W_beta = (const float*)d_in[8];
    const float* b_beta = (const float*)d_in[9];

    float* out = (float*)d_out;
    float* out_z = out;
    float* out_alpha = out + (size_t)BATCH * ENC;

    cudaFuncSetAttribute(att_gemm_mma, cudaFuncAttributeMaxDynamicSharedMemorySize, DYN_BYTES);

    prep_w<<<dim3(ENC / 64, ATTD / 64), 256>>>(W_enc);
    att2_kernel<<<BATCH, 256>>>(h, W_dec, b_dec, b_enc, W_beta, b_beta);
    att_gemm_mma<<<MAIN_CTAS + QTILES, NTHREADS, DYN_BYTES>>>(x, W_full);
    softmax_z_kernel<<<BATCH, 256>>>(x, out_alpha, out_z);
}

// round 15
// speedup vs baseline: 1.0717x; 1.0717x over previous
#include <cuda_runtime.h>
#include <cuda_fp16.h>
#include <cstdint>
#include <math.h>

#define ENC 2048
#define DEC 512
#define ATTD 512
#define BATCH 256
#define LSEQ 196
#define MROWS (BATCH * LSEQ)      // 50176
#define TILE_M 128
#define NCTA (MROWS / TILE_M)     // 392
#define KBLK 64
#define NKB (ENC / KBLK)          // 32
#define NB_CHUNKS 2               // 512 / 256
#define NSTG 3
#define XSTG 16384                // x: 128 rows x 64k x 2B
#define WSTG 32768                // W: 256 rows x 64k x 2B
#define WBASE (NSTG * XSTG)       // 49152
#define DYN_BYTES (WBASE + NSTG * WSTG + 128)  // 147584
#define NTHREADS 512

// ---------------- scratch globals ----------------
__device__ float g_att2[BATCH * ATTD];
__device__ float g_gate[BATCH];
__device__ float g_att[MROWS];
// W transposed fp16: [n=512][k=2048]
__device__ __align__(16) unsigned char g_Wt[512u * 2048u * 2u];
// x as fp16 (side-written by GEMM, consumed by z): [m][k]
__device__ __align__(16) __half g_Xh[(size_t)MROWS * ENC];

// ---------------- helpers ----------------
__device__ __forceinline__ uint32_t smem_u32(const void* p) {
    uint32_t a;
    asm("{ .reg .u64 t; cvta.to.shared.u64 t, %1; cvt.u32.u64 %0, t; }" : "=r"(a) : "l"(p));
    return a;
}
__device__ __forceinline__ uint32_t packh2(__half a, __half b) {
    __half2 t = __halves2half2(a, b);
    return *reinterpret_cast<uint32_t*>(&t);
}
#define LDSM_X4(r, addr) \
    asm volatile("ldmatrix.sync.aligned.m8n8.x4.shared.b16 {%0,%1,%2,%3}, [%4];" \
        : "=r"((r)[0]), "=r"((r)[1]), "=r"((r)[2]), "=r"((r)[3]) : "r"(addr))
#define MMA_F16F32(c, a, b) \
    asm volatile("mma.sync.aligned.m16n8k16.row.col.f32.f16.f16.f32 " \
        "{%0,%1,%2,%3}, {%4,%5,%6,%7}, {%8,%9}, {%0,%1,%2,%3};" \
        : "+f"((c)[0]), "+f"((c)[1]), "+f"((c)[2]), "+f"((c)[3]) \
        : "r"((a)[0]), "r"((a)[1]), "r"((a)[2]), "r"((a)[3]), "r"((b)[0]), "r"((b)[1]))
#define CP_ASYNC16(dst, src) \
    asm volatile("cp.async.ca.shared.global [%0], [%1], 16;" :: "r"(dst), "l"(src) : "memory")
#define CP_COMMIT() asm volatile("cp.async.commit_group;" ::: "memory")
#define CP_WAIT1()  asm volatile("cp.async.wait_group 1;" ::: "memory")
#define CP_WAIT0()  asm volatile("cp.async.wait_group 0;" ::: "memory")

// ---------------------------------------------------------------------------
// prep_w: W_enc [2048 k][512 n] fp32 -> g_Wt fp16 [n][k]
// ---------------------------------------------------------------------------
__global__ __launch_bounds__(256) void prep_w(const float* __restrict__ W_enc) {
    __shared__ float tile[64][65];
    const int k0 = blockIdx.x * 64, n0 = blockIdx.y * 64;
    const int tid = threadIdx.x;
    for (int i = tid; i < 64 * 64; i += 256) {
        int kk = i >> 6, nn = i & 63;
        tile[kk][nn] = W_enc[(size_t)(k0 + kk) * ATTD + n0 + nn];
    }
    __syncthreads();
    for (int i = tid; i < 512; i += 256) {
        int nn = i >> 3, ch = i & 7;
        uint32_t w[4];
#pragma unroll
        for (int j = 0; j < 4; j++) {
            w[j] = packh2(__float2half_rn(tile[ch * 8 + 2 * j][nn]),
                          __float2half_rn(tile[ch * 8 + 2 * j + 1][nn]));
        }
        *reinterpret_cast<uint4*>(g_Wt + (size_t)(n0 + nn) * 4096 +
                                  (size_t)(k0 + ch * 8) * 2) =
            make_uint4(w[0], w[1], w[2], w[3]);
    }
}

// ---------------------------------------------------------------------------
// att2 + gate (fp32)
// ---------------------------------------------------------------------------
__global__ __launch_bounds__(256) void att2_kernel(
    const float* __restrict__ h, const float* __restrict__ W_dec,
    const float* __restrict__ b_dec, const float* __restrict__ b_enc,
    const float* __restrict__ W_beta, const float* __restrict__ b_beta) {
    int b = blockIdx.x, t = threadIdx.x;
    __shared__ float hs[DEC];
    __shared__ float red[256];
    hs[t] = h[b * DEC + t];
    hs[t + 256] = h[b * DEC + t + 256];
    __syncthreads();
    float acc0 = 0.f, acc1 = 0.f;
#pragma unroll 8
    for (int k = 0; k < DEC; k++) {
        float hv = hs[k];
        acc0 += hv * W_dec[k * ATTD + t];
        acc1 += hv * W_dec[k * ATTD + t + 256];
    }
    g_att2[b * ATTD + t] = acc0 + b_dec[t] + b_enc[t];
    g_att2[b * ATTD + t + 256] = acc1 + b_dec[t + 256] + b_enc[t + 256];
    float p = hs[t] * W_beta[t] + hs[t + 256] * W_beta[t + 256];
    red[t] = p;
    __syncthreads();
    for (int s = 128; s > 0; s >>= 1) {
        if (t < s) red[t] += red[t + s];
        __syncthreads();
    }
    if (t == 0) g_gate[b] = 1.f / (1.f + expf(-(red[0] + b_beta[0])));
}

// ---------------------------------------------------------------------------
// Main GEMM (R11 config): single-pass fp16, KBLK=64, 3-stage pipeline,
// 512 threads = 16 warps (4m x 4n), warp m32 x n64, 2 n-chunks of 256.
// During nb==0, side-writes the fp16 x copy to g_Xh for the z kernel.
// ---------------------------------------------------------------------------
__global__ __launch_bounds__(NTHREADS, 1) void att_gemm_mma(
    const float* __restrict__ x, const float* __restrict__ W_full) {
    extern __shared__ unsigned char dynraw[];
    __shared__ float wf_s[ATTD];
    __shared__ float att_acc[TILE_M];

    const int tid = threadIdx.x;
    const int lane = tid & 31;
    const int wid = tid >> 5;
    const int wm = wid >> 2;   // 0..3
    const int wn = wid & 3;    // 0..3
    const int row0 = blockIdx.x * TILE_M;

    uint32_t rawb = smem_u32(dynraw);
    uint32_t dynb = (rawb + 127u) & ~127u;
    unsigned char* dyn = dynraw + (dynb - rawb);

    wf_s[tid] = W_full[tid];
    if (tid < TILE_M) att_acc[tid] = 0.f;
    __syncthreads();

    const int xm = tid >> 2, xq = tid & 3;
    const int xs7 = xm & 7;
    const float4* xg = reinterpret_cast<const float4*>(x) +
                       ((size_t)(row0 + xm) * ENC) / 4 + xq * 4;
    // fp16 side-write base: row (row0+xm), element offset xq*16
    uint4* xh_out = reinterpret_cast<uint4*>(
        g_Xh + (size_t)(row0 + xm) * ENC + xq * 16);

    const int a_r = wm * 32 + (lane & 15);
    const int a_hi = lane >> 4;
    const int b_r = wn * 64 + (lane & 7) + ((lane >> 1) & 8);
    const int b_hi = (lane >> 3) & 1;

    for (int nb = 0; nb < NB_CHUNKS; nb++) {
        float acc[2][8][4];
#pragma unroll
        for (int mt = 0; mt < 2; mt++)
#pragma unroll
            for (int nt = 0; nt < 8; nt++)
#pragma unroll
                for (int q = 0; q < 4; q++) acc[mt][nt][q] = 0.f;

        {   // x stage 0
            float4 v0 = xg[0], v1 = xg[1], v2 = xg[2], v3 = xg[3];
            float e[16] = {v0.x, v0.y, v0.z, v0.w, v1.x, v1.y, v1.z, v1.w,
                           v2.x, v2.y, v2.z, v2.w, v3.x, v3.y, v3.z, v3.w};
            uint32_t hw[8];
#pragma unroll
            for (int q = 0; q < 8; q++)
                hw[q] = packh2(__float2half_rn(e[2 * q]), __float2half_rn(e[2 * q + 1]));
            int c0 = 2 * xq;
            *reinterpret_cast<uint4*>(dyn + xm * 128 + ((c0 ^ xs7) << 4)) =
                make_uint4(hw[0], hw[1], hw[2], hw[3]);
            *reinterpret_cast<uint4*>(dyn + xm * 128 + (((c0 + 1) ^ xs7) << 4)) =
                make_uint4(hw[4], hw[5], hw[6], hw[7]);
            if (nb == 0) {
                xh_out[0] = make_uint4(hw[0], hw[1], hw[2], hw[3]);
                xh_out[1] = make_uint4(hw[4], hw[5], hw[6], hw[7]);
            }
        }
#pragma unroll
        for (int p = 0; p < 2; p++) {
#pragma unroll
            for (int j = 0; j < 4; j++) {
                int i = tid + NTHREADS * j;
                int row = i >> 3, c = i & 7;
                uint32_t dst = dynb + WBASE + p * WSTG + row * 128 + ((c ^ (row & 7)) << 4);
                const unsigned char* src = g_Wt +
                    (size_t)(nb * 256 + row) * 4096 + (size_t)(p * KBLK + c * 8) * 2;
                CP_ASYNC16(dst, src);
            }
            CP_COMMIT();
        }

        for (int kblk = 0; kblk < NKB; kblk++) {
            const int st = kblk % NSTG;
            const bool more = (kblk + 1 < NKB);
            float4 xr0, xr1, xr2, xr3;
            if (more) {
                const float4* p = xg + (kblk + 1) * (KBLK / 4);
                xr0 = p[0]; xr1 = p[1]; xr2 = p[2]; xr3 = p[3];
            }
            CP_WAIT1();
            __syncthreads();

            if (kblk + 2 < NKB) {
                const int ws = (kblk + 2) % NSTG;
#pragma unroll
                for (int j = 0; j < 4; j++) {
                    int i = tid + NTHREADS * j;
                    int row = i >> 3, c = i & 7;
                    uint32_t dst = dynb + WBASE + ws * WSTG + row * 128 +
                                   ((c ^ (row & 7)) << 4);
                    const unsigned char* src = g_Wt +
                        (size_t)(nb * 256 + row) * 4096 +
                        (size_t)((kblk + 2) * KBLK + c * 8) * 2;
                    CP_ASYNC16(dst, src);
                }
            }
            CP_COMMIT();

            {
                const uint32_t xsb = dynb + st * XSTG;
                const uint32_t wsb = dynb + WBASE + st * WSTG;
#pragma unroll
                for (int ks = 0; ks < 4; ks++) {
                    uint32_t ah[2][4];
#pragma unroll
                    for (int mt = 0; mt < 2; mt++) {
                        int row = a_r + mt * 16;
                        uint32_t ad = xsb + row * 128 +
                                      (((ks * 2 + a_hi) ^ (row & 7)) << 4);
                        LDSM_X4(ah[mt], ad);
                    }
#pragma unroll
                    for (int ntp = 0; ntp < 4; ntp++) {
                        int row = b_r + ntp * 16;
                        uint32_t bd = wsb + row * 128 +
                                      (((ks * 2 + b_hi) ^ (row & 7)) << 4);
                        uint32_t bh[4];
                        LDSM_X4(bh, bd);
#pragma unroll
                        for (int mt = 0; mt < 2; mt++) {
                            MMA_F16F32(acc[mt][2 * ntp],     ah[mt], bh + 0);
                            MMA_F16F32(acc[mt][2 * ntp + 1], ah[mt], bh + 2);
                        }
                    }
                }
            }

            if (more) {
                const int xs = (kblk + 1) % NSTG;
                float e[16] = {xr0.x, xr0.y, xr0.z, xr0.w, xr1.x, xr1.y, xr1.z, xr1.w,
                               xr2.x, xr2.y, xr2.z, xr2.w, xr3.x, xr3.y, xr3.z, xr3.w};
                uint32_t hw[8];
#pragma unroll
                for (int q = 0; q < 8; q++)
                    hw[q] = packh2(__float2half_rn(e[2 * q]), __float2half_rn(e[2 * q + 1]));
                unsigned char* xb = dyn + xs * XSTG;
                int c0 = 2 * xq;
                *reinterpret_cast<uint4*>(xb + xm * 128 + ((c0 ^ xs7) << 4)) =
                    make_uint4(hw[0], hw[1], hw[2], hw[3]);
                *reinterpret_cast<uint4*>(xb + xm * 128 + (((c0 + 1) ^ xs7) << 4)) =
                    make_uint4(hw[4], hw[5], hw[6], hw[7]);
                if (nb == 0) {
                    uint4* o = xh_out + (size_t)(kblk + 1) * (KBLK / 8);
                    o[0] = make_uint4(hw[0], hw[1], hw[2], hw[3]);
                    o[1] = make_uint4(hw[4], hw[5], hw[6], hw[7]);
                }
            }
        }
        CP_WAIT0();
        __syncthreads();

#pragma unroll
        for (int mt = 0; mt < 2; mt++)
#pragma unroll
            for (int rh = 0; rh < 2; rh++) {
                int ml = wm * 32 + mt * 16 + (lane >> 2) + rh * 8;
                int gm = row0 + ml;
                int b = gm / LSEQ;
                const float* a2 = g_att2 + (size_t)b * ATTD + nb * 256 + wn * 64;
                const float* wfp = wf_s + nb * 256 + wn * 64;
                float s = 0.f;
#pragma unroll
                for (int nt = 0; nt < 8; nt++) {
#pragma unroll
                    for (int e2 = 0; e2 < 2; e2++) {
                        int nn = nt * 8 + (lane & 3) * 2 + e2;
                        float v = acc[mt][nt][rh * 2 + e2] + __ldg(a2 + nn);
                        s += fmaxf(v, 0.f) * wfp[nn];
                    }
                }
                s += __shfl_xor_sync(0xFFFFFFFF, s, 1);
                s += __shfl_xor_sync(0xFFFFFFFF, s, 2);
                if ((lane & 3) == 0) atomicAdd(&att_acc[ml], s);
            }
        __syncthreads();
    }

    if (tid < TILE_M) g_att[row0 + tid] = att_acc[tid];
}

// ---------------------------------------------------------------------------
// softmax over L (separate — fusion with z measured slower in R13)
// ---------------------------------------------------------------------------
__global__ __launch_bounds__(256) void softmax_kernel(float* __restrict__ out_alpha) {
    int b = blockIdx.x, t = threadIdx.x;
    __shared__ float sred[256];
    float v = (t < LSEQ) ? g_att[b * LSEQ + t] : -1e30f;
    sred[t] = v;
    __syncthreads();
    for (int s = 128; s > 0; s >>= 1) {
        if (t < s) sred[t] = fmaxf(sred[t], sred[t + s]);
        __syncthreads();
    }
    float m = sred[0];
    __syncthreads();
    float e = (t < LSEQ) ? expf(v - m) : 0.f;
    sred[t] = e;
    __syncthreads();
    for (int s = 128; s > 0; s >>= 1) {
        if (t < s) sred[t] += sred[t + s];
        __syncthreads();
    }
    float inv = 1.f / sred[0];
    if (t < LSEQ) out_alpha[b * LSEQ + t] = e * inv;
}

// ---------------------------------------------------------------------------
// z from fp16 x copy: one block per batch; each thread owns ONE uint4 column
// (8 halves = full row coverage with 256 threads). MLP from l-unrolling.
// ---------------------------------------------------------------------------
__global__ __launch_bounds__(256) void z_kernel(
    const float* __restrict__ alpha, float* __restrict__ out_z) {
    int b = blockIdx.x;
    int t = threadIdx.x;
    __shared__ float sal[LSEQ];
    for (int i = t; i < LSEQ; i += 256) sal[i] = alpha[b * LSEQ + i];
    __syncthreads();
    const uint4* xp = reinterpret_cast<const uint4*>(g_Xh + (size_t)b * LSEQ * ENC) + t;
    float a0[8] = {0, 0, 0, 0, 0, 0, 0, 0};
#pragma unroll 4
    for (int l = 0; l < LSEQ; l++) {
        float a = sal[l];
        uint4 v = __ldg(xp + (size_t)l * (ENC / 8));
        const __half2* hh = reinterpret_cast<const __half2*>(&v);
#pragma unroll
        for (int j = 0; j < 4; j++) {
            float2 f = __half22float2(hh[j]);
            a0[2 * j] += a * f.x;
            a0[2 * j + 1] += a * f.y;
        }
    }
    float g = g_gate[b];
    float4 oa = {g * a0[0], g * a0[1], g * a0[2], g * a0[3]};
    float4 ob = {g * a0[4], g * a0[5], g * a0[6], g * a0[7]};
    float4* zp = reinterpret_cast<float4*>(out_z + (size_t)b * ENC);
    zp[2 * t] = oa;
    zp[2 * t + 1] = ob;
}

// ---------------------------------------------------------------------------
extern "C" void kernel_launch(void* const* d_in, const int* in_sizes, int n_in,
                              void* d_out, int out_size) {
    const float* x      = (const float*)d_in[0];
    const float* h      = (const float*)d_in[1];
    const float* W_enc  = (const float*)d_in[2];
    const float* b_enc  = (const float*)d_in[3];
    const float* W_dec  = (const float*)d_in[4];
    const float* b_dec  = (const float*)d_in[5];
    const float* W_full = (const float*)d_in[6];
    // d_in[7] = b_full: softmax-invariant, unused.
    const float* W_beta = (const float*)d_in[8];
    const float* b_beta = (const float*)d_in[9];

    float* out = (float*)d_out;
    float* out_z = out;
    float* out_alpha = out + (size_t)BATCH * ENC;

    cudaFuncSetAttribute(att_gemm_mma, cudaFuncAttributeMaxDynamicSharedMemorySize, DYN_BYTES);

    prep_w<<<dim3(ENC / 64, ATTD / 64), 256>>>(W_enc);
    att2_kernel<<<BATCH, 256>>>(h, W_dec, b_dec, b_enc, W_beta, b_beta);
    att_gemm_mma<<<NCTA, NTHREADS, DYN_BYTES>>>(x, W_full);
    softmax_kernel<<<BATCH, 256>>>(out_alpha);
    z_kernel<<<BATCH, 256>>>(out_alpha, out_z);
}

// round 16
// speedup vs baseline: 1.0928x; 1.0197x over previous
#include <cuda_runtime.h>
#include <cuda_fp16.h>
#include <cstdint>
#include <math.h>

#define ENC 2048
#define DEC 512
#define ATTD 512
#define BATCH 256
#define LSEQ 196
#define MROWS (BATCH * LSEQ)      // 50176
#define TILE_M 128
#define NCTA (MROWS / TILE_M)     // 392
#define KBLK 64
#define NKB (ENC / KBLK)          // 32
#define NB_CHUNKS 2               // 512 / 256
#define NSTG 3
#define XSTG 16384                // x: 128 rows x 64k x 2B
#define WSTG 32768                // W: 256 rows x 64k x 2B
#define WBASE (NSTG * XSTG)       // 49152
#define DYN_BYTES (WBASE + NSTG * WSTG + 128)  // 147584
#define NTHREADS 512

// ---------------- scratch globals ----------------
__device__ float g_att2[BATCH * ATTD];
__device__ float g_gate[BATCH];
__device__ float g_att[MROWS];
// W transposed fp16: [n=512][k=2048]
__device__ __align__(16) unsigned char g_Wt[512u * 2048u * 2u];
// x as fp16 (side-written by GEMM with .cs, consumed by z): [m][k]
__device__ __align__(16) __half g_Xh[(size_t)MROWS * ENC];

// ---------------- helpers ----------------
__device__ __forceinline__ uint32_t smem_u32(const void* p) {
    uint32_t a;
    asm("{ .reg .u64 t; cvta.to.shared.u64 t, %1; cvt.u32.u64 %0, t; }" : "=r"(a) : "l"(p));
    return a;
}
__device__ __forceinline__ uint32_t packh2(__half a, __half b) {
    __half2 t = __halves2half2(a, b);
    return *reinterpret_cast<uint32_t*>(&t);
}
__device__ __forceinline__ void stg_cs_128(void* p, uint4 v) {
    asm volatile("st.global.cs.v4.b32 [%0], {%1, %2, %3, %4};"
        :: "l"(p), "r"(v.x), "r"(v.y), "r"(v.z), "r"(v.w) : "memory");
}
#define LDSM_X4(r, addr) \
    asm volatile("ldmatrix.sync.aligned.m8n8.x4.shared.b16 {%0,%1,%2,%3}, [%4];" \
        : "=r"((r)[0]), "=r"((r)[1]), "=r"((r)[2]), "=r"((r)[3]) : "r"(addr))
#define MMA_F16F32(c, a, b) \
    asm volatile("mma.sync.aligned.m16n8k16.row.col.f32.f16.f16.f32 " \
        "{%0,%1,%2,%3}, {%4,%5,%6,%7}, {%8,%9}, {%0,%1,%2,%3};" \
        : "+f"((c)[0]), "+f"((c)[1]), "+f"((c)[2]), "+f"((c)[3]) \
        : "r"((a)[0]), "r"((a)[1]), "r"((a)[2]), "r"((a)[3]), "r"((b)[0]), "r"((b)[1]))
#define CP_ASYNC16(dst, src) \
    asm volatile("cp.async.ca.shared.global [%0], [%1], 16;" :: "r"(dst), "l"(src) : "memory")
#define CP_COMMIT() asm volatile("cp.async.commit_group;" ::: "memory")
#define CP_WAIT1()  asm volatile("cp.async.wait_group 1;" ::: "memory")
#define CP_WAIT0()  asm volatile("cp.async.wait_group 0;" ::: "memory")

// ---------------------------------------------------------------------------
// prep_w: W_enc [2048 k][512 n] fp32 -> g_Wt fp16 [n][k]
// ---------------------------------------------------------------------------
__global__ __launch_bounds__(256) void prep_w(const float* __restrict__ W_enc) {
    __shared__ float tile[64][65];
    const int k0 = blockIdx.x * 64, n0 = blockIdx.y * 64;
    const int tid = threadIdx.x;
    for (int i = tid; i < 64 * 64; i += 256) {
        int kk = i >> 6, nn = i & 63;
        tile[kk][nn] = W_enc[(size_t)(k0 + kk) * ATTD + n0 + nn];
    }
    __syncthreads();
    for (int i = tid; i < 512; i += 256) {
        int nn = i >> 3, ch = i & 7;
        uint32_t w[4];
#pragma unroll
        for (int j = 0; j < 4; j++) {
            w[j] = packh2(__float2half_rn(tile[ch * 8 + 2 * j][nn]),
                          __float2half_rn(tile[ch * 8 + 2 * j + 1][nn]));
        }
        *reinterpret_cast<uint4*>(g_Wt + (size_t)(n0 + nn) * 4096 +
                                  (size_t)(k0 + ch * 8) * 2) =
            make_uint4(w[0], w[1], w[2], w[3]);
    }
}

// ---------------------------------------------------------------------------
// att2 + gate (fp32)
// ---------------------------------------------------------------------------
__global__ __launch_bounds__(256) void att2_kernel(
    const float* __restrict__ h, const float* __restrict__ W_dec,
    const float* __restrict__ b_dec, const float* __restrict__ b_enc,
    const float* __restrict__ W_beta, const float* __restrict__ b_beta) {
    int b = blockIdx.x, t = threadIdx.x;
    __shared__ float hs[DEC];
    __shared__ float red[256];
    hs[t] = h[b * DEC + t];
    hs[t + 256] = h[b * DEC + t + 256];
    __syncthreads();
    float acc0 = 0.f, acc1 = 0.f;
#pragma unroll 8
    for (int k = 0; k < DEC; k++) {
        float hv = hs[k];
        acc0 += hv * W_dec[k * ATTD + t];
        acc1 += hv * W_dec[k * ATTD + t + 256];
    }
    g_att2[b * ATTD + t] = acc0 + b_dec[t] + b_enc[t];
    g_att2[b * ATTD + t + 256] = acc1 + b_dec[t + 256] + b_enc[t + 256];
    float p = hs[t] * W_beta[t] + hs[t + 256] * W_beta[t + 256];
    red[t] = p;
    __syncthreads();
    for (int s = 128; s > 0; s >>= 1) {
        if (t < s) red[t] += red[t + s];
        __syncthreads();
    }
    if (t == 0) g_gate[b] = 1.f / (1.f + expf(-(red[0] + b_beta[0])));
}

// ---------------------------------------------------------------------------
// Main GEMM (R11 config): single-pass fp16, KBLK=64, 3-stage pipeline,
// 512 threads = 16 warps (4m x 4n), warp m32 x n64, 2 n-chunks of 256.
// During nb==0, side-writes the fp16 x copy to g_Xh with st.global.cs
// (streaming — avoids evicting the resident W tiles from L2).
// ---------------------------------------------------------------------------
__global__ __launch_bounds__(NTHREADS, 1) void att_gemm_mma(
    const float* __restrict__ x, const float* __restrict__ W_full) {
    extern __shared__ unsigned char dynraw[];
    __shared__ float wf_s[ATTD];
    __shared__ float att_acc[TILE_M];

    const int tid = threadIdx.x;
    const int lane = tid & 31;
    const int wid = tid >> 5;
    const int wm = wid >> 2;   // 0..3
    const int wn = wid & 3;    // 0..3
    const int row0 = blockIdx.x * TILE_M;

    uint32_t rawb = smem_u32(dynraw);
    uint32_t dynb = (rawb + 127u) & ~127u;
    unsigned char* dyn = dynraw + (dynb - rawb);

    wf_s[tid] = W_full[tid];
    if (tid < TILE_M) att_acc[tid] = 0.f;
    __syncthreads();

    const int xm = tid >> 2, xq = tid & 3;
    const int xs7 = xm & 7;
    const float4* xg = reinterpret_cast<const float4*>(x) +
                       ((size_t)(row0 + xm) * ENC) / 4 + xq * 4;
    // fp16 side-write base: row (row0+xm), element offset xq*16
    uint4* xh_out = reinterpret_cast<uint4*>(
        g_Xh + (size_t)(row0 + xm) * ENC + xq * 16);

    const int a_r = wm * 32 + (lane & 15);
    const int a_hi = lane >> 4;
    const int b_r = wn * 64 + (lane & 7) + ((lane >> 1) & 8);
    const int b_hi = (lane >> 3) & 1;

    for (int nb = 0; nb < NB_CHUNKS; nb++) {
        float acc[2][8][4];
#pragma unroll
        for (int mt = 0; mt < 2; mt++)
#pragma unroll
            for (int nt = 0; nt < 8; nt++)
#pragma unroll
                for (int q = 0; q < 4; q++) acc[mt][nt][q] = 0.f;

        {   // x stage 0
            float4 v0 = xg[0], v1 = xg[1], v2 = xg[2], v3 = xg[3];
            float e[16] = {v0.x, v0.y, v0.z, v0.w, v1.x, v1.y, v1.z, v1.w,
                           v2.x, v2.y, v2.z, v2.w, v3.x, v3.y, v3.z, v3.w};
            uint32_t hw[8];
#pragma unroll
            for (int q = 0; q < 8; q++)
                hw[q] = packh2(__float2half_rn(e[2 * q]), __float2half_rn(e[2 * q + 1]));
            int c0 = 2 * xq;
            *reinterpret_cast<uint4*>(dyn + xm * 128 + ((c0 ^ xs7) << 4)) =
                make_uint4(hw[0], hw[1], hw[2], hw[3]);
            *reinterpret_cast<uint4*>(dyn + xm * 128 + (((c0 + 1) ^ xs7) << 4)) =
                make_uint4(hw[4], hw[5], hw[6], hw[7]);
            if (nb == 0) {
                stg_cs_128(xh_out + 0, make_uint4(hw[0], hw[1], hw[2], hw[3]));
                stg_cs_128(xh_out + 1, make_uint4(hw[4], hw[5], hw[6], hw[7]));
            }
        }
#pragma unroll
        for (int p = 0; p < 2; p++) {
#pragma unroll
            for (int j = 0; j < 4; j++) {
                int i = tid + NTHREADS * j;
                int row = i >> 3, c = i & 7;
                uint32_t dst = dynb + WBASE + p * WSTG + row * 128 + ((c ^ (row & 7)) << 4);
                const unsigned char* src = g_Wt +
                    (size_t)(nb * 256 + row) * 4096 + (size_t)(p * KBLK + c * 8) * 2;
                CP_ASYNC16(dst, src);
            }
            CP_COMMIT();
        }

        for (int kblk = 0; kblk < NKB; kblk++) {
            const int st = kblk % NSTG;
            const bool more = (kblk + 1 < NKB);
            float4 xr0, xr1, xr2, xr3;
            if (more) {
                const float4* p = xg + (kblk + 1) * (KBLK / 4);
                xr0 = p[0]; xr1 = p[1]; xr2 = p[2]; xr3 = p[3];
            }
            CP_WAIT1();
            __syncthreads();

            if (kblk + 2 < NKB) {
                const int ws = (kblk + 2) % NSTG;
#pragma unroll
                for (int j = 0; j < 4; j++) {
                    int i = tid + NTHREADS * j;
                    int row = i >> 3, c = i & 7;
                    uint32_t dst = dynb + WBASE + ws * WSTG + row * 128 +
                                   ((c ^ (row & 7)) << 4);
                    const unsigned char* src = g_Wt +
                        (size_t)(nb * 256 + row) * 4096 +
                        (size_t)((kblk + 2) * KBLK + c * 8) * 2;
                    CP_ASYNC16(dst, src);
                }
            }
            CP_COMMIT();

            {
                const uint32_t xsb = dynb + st * XSTG;
                const uint32_t wsb = dynb + WBASE + st * WSTG;
#pragma unroll
                for (int ks = 0; ks < 4; ks++) {
                    uint32_t ah[2][4];
#pragma unroll
                    for (int mt = 0; mt < 2; mt++) {
                        int row = a_r + mt * 16;
                        uint32_t ad = xsb + row * 128 +
                                      (((ks * 2 + a_hi) ^ (row & 7)) << 4);
                        LDSM_X4(ah[mt], ad);
                    }
#pragma unroll
                    for (int ntp = 0; ntp < 4; ntp++) {
                        int row = b_r + ntp * 16;
                        uint32_t bd = wsb + row * 128 +
                                      (((ks * 2 + b_hi) ^ (row & 7)) << 4);
                        uint32_t bh[4];
                        LDSM_X4(bh, bd);
#pragma unroll
                        for (int mt = 0; mt < 2; mt++) {
                            MMA_F16F32(acc[mt][2 * ntp],     ah[mt], bh + 0);
                            MMA_F16F32(acc[mt][2 * ntp + 1], ah[mt], bh + 2);
                        }
                    }
                }
            }

            if (more) {
                const int xs = (kblk + 1) % NSTG;
                float e[16] = {xr0.x, xr0.y, xr0.z, xr0.w, xr1.x, xr1.y, xr1.z, xr1.w,
                               xr2.x, xr2.y, xr2.z, xr2.w, xr3.x, xr3.y, xr3.z, xr3.w};
                uint32_t hw[8];
#pragma unroll
                for (int q = 0; q < 8; q++)
                    hw[q] = packh2(__float2half_rn(e[2 * q]), __float2half_rn(e[2 * q + 1]));
                unsigned char* xb = dyn + xs * XSTG;
                int c0 = 2 * xq;
                *reinterpret_cast<uint4*>(xb + xm * 128 + ((c0 ^ xs7) << 4)) =
                    make_uint4(hw[0], hw[1], hw[2], hw[3]);
                *reinterpret_cast<uint4*>(xb + xm * 128 + (((c0 + 1) ^ xs7) << 4)) =
                    make_uint4(hw[4], hw[5], hw[6], hw[7]);
                if (nb == 0) {
                    uint4* o = xh_out + (size_t)(kblk + 1) * (KBLK / 8);
                    stg_cs_128(o + 0, make_uint4(hw[0], hw[1], hw[2], hw[3]));
                    stg_cs_128(o + 1, make_uint4(hw[4], hw[5], hw[6], hw[7]));
                }
            }
        }
        CP_WAIT0();
        __syncthreads();

#pragma unroll
        for (int mt = 0; mt < 2; mt++)
#pragma unroll
            for (int rh = 0; rh < 2; rh++) {
                int ml = wm * 32 + mt * 16 + (lane >> 2) + rh * 8;
                int gm = row0 + ml;
                int b = gm / LSEQ;
                const float* a2 = g_att2 + (size_t)b * ATTD + nb * 256 + wn * 64;
                const float* wfp = wf_s + nb * 256 + wn * 64;
                float s = 0.f;
#pragma unroll
                for (int nt = 0; nt < 8; nt++) {
#pragma unroll
                    for (int e2 = 0; e2 < 2; e2++) {
                        int nn = nt * 8 + (lane & 3) * 2 + e2;
                        float v = acc[mt][nt][rh * 2 + e2] + __ldg(a2 + nn);
                        s += fmaxf(v, 0.f) * wfp[nn];
                    }
                }
                s += __shfl_xor_sync(0xFFFFFFFF, s, 1);
                s += __shfl_xor_sync(0xFFFFFFFF, s, 2);
                if ((lane & 3) == 0) atomicAdd(&att_acc[ml], s);
            }
        __syncthreads();
    }

    if (tid < TILE_M) g_att[row0 + tid] = att_acc[tid];
}

// ---------------------------------------------------------------------------
// softmax over L
// ---------------------------------------------------------------------------
__global__ __launch_bounds__(256) void softmax_kernel(float* __restrict__ out_alpha) {
    int b = blockIdx.x, t = threadIdx.x;
    __shared__ float sred[256];
    float v = (t < LSEQ) ? g_att[b * LSEQ + t] : -1e30f;
    sred[t] = v;
    __syncthreads();
    for (int s = 128; s > 0; s >>= 1) {
        if (t < s) sred[t] = fmaxf(sred[t], sred[t + s]);
        __syncthreads();
    }
    float m = sred[0];
    __syncthreads();
    float e = (t < LSEQ) ? expf(v - m) : 0.f;
    sred[t] = e;
    __syncthreads();
    for (int s = 128; s > 0; s >>= 1) {
        if (t < s) sred[t] += sred[t + s];
        __syncthreads();
    }
    float inv = 1.f / sred[0];
    if (t < LSEQ) out_alpha[b * LSEQ + t] = e * inv;
}

// ---------------------------------------------------------------------------
// z from fp16 x copy: grid (BATCH, 2), 128 threads; each thread owns one
// uint4 (8 halves) in its half of the row. 512 CTAs for occupancy.
// ---------------------------------------------------------------------------
__global__ __launch_bounds__(128) void z_kernel(
    const float* __restrict__ alpha, float* __restrict__ out_z) {
    int b = blockIdx.x;
    int half = blockIdx.y;            // 0 or 1
    int t = threadIdx.x;              // 0..127
    int col = half * 128 + t;         // uint4 column, 0..255
    __shared__ float sal[LSEQ];
    for (int i = t; i < LSEQ; i += 128) sal[i] = alpha[b * LSEQ + i];
    __syncthreads();
    const uint4* xp = reinterpret_cast<const uint4*>(g_Xh + (size_t)b * LSEQ * ENC) + col;
    float a0[8] = {0, 0, 0, 0, 0, 0, 0, 0};
#pragma unroll 4
    for (int l = 0; l < LSEQ; l++) {
        float a = sal[l];
        uint4 v = __ldg(xp + (size_t)l * (ENC / 8));
        const __half2* hh = reinterpret_cast<const __half2*>(&v);
#pragma unroll
        for (int j = 0; j < 4; j++) {
            float2 f = __half22float2(hh[j]);
            a0[2 * j] += a * f.x;
            a0[2 * j + 1] += a * f.y;
        }
    }
    float g = g_gate[b];
    float4 oa = {g * a0[0], g * a0[1], g * a0[2], g * a0[3]};
    float4 ob = {g * a0[4], g * a0[5], g * a0[6], g * a0[7]};
    float4* zp = reinterpret_cast<float4*>(out_z + (size_t)b * ENC);
    zp[2 * col] = oa;
    zp[2 * col + 1] = ob;
}

// ---------------------------------------------------------------------------
extern "C" void kernel_launch(void* const* d_in, const int* in_sizes, int n_in,
                              void* d_out, int out_size) {
    const float* x      = (const float*)d_in[0];
    const float* h      = (const float*)d_in[1];
    const float* W_enc  = (const float*)d_in[2];
    const float* b_enc  = (const float*)d_in[3];
    const float* W_dec  = (const float*)d_in[4];
    const float* b_dec  = (const float*)d_in[5];
    const float* W_full = (const float*)d_in[6];
    // d_in[7] = b_full: softmax-invariant, unused.
    const float* W_beta = (const float*)d_in[8];
    const float* b_beta = (const float*)d_in[9];

    float* out = (float*)d_out;
    float* out_z = out;
    float* out_alpha = out + (size_t)BATCH * ENC;

    cudaFuncSetAttribute(att_gemm_mma, cudaFuncAttributeMaxDynamicSharedMemorySize, DYN_BYTES);

    prep_w<<<dim3(ENC / 64, ATTD / 64), 256>>>(W_enc);
    att2_kernel<<<BATCH, 256>>>(h, W_dec, b_dec, b_enc, W_beta, b_beta);
    att_gemm_mma<<<NCTA, NTHREADS, DYN_BYTES>>>(x, W_full);
    softmax_kernel<<<BATCH, 256>>>(out_alpha);
    z_kernel<<<dim3(BATCH, 2), 128>>>(out_alpha, out_z);
}